// round 8
// baseline (speedup 1.0000x reference)
#include <cuda_runtime.h>
#include <cuda_fp16.h>

// ---------------- problem constants ----------------
#define Bb   2
#define Ss   2048
#define DMm  256
#define DIi  512
#define NN   16
#define RR   32
#define MM   (Bb*Ss)          // 4096 rows per chain
#define M2   (2*MM)           // 8192 rows: [fwd | reversed]
#define CHUNK 32
#define NCH  (Ss/CHUNK)       // 64 chunks per sequence
#define NSEQ 4                // 4 sequences total (2 fwd + 2 rev)
#define KS   4                // split-K for x-proj

// ---------------- device scratch ----------------
__device__ float  g_res [M2*DMm];
__device__ __half g_xs  [M2*DIi];
__device__ __half g_z   [M2*DIi];
__device__ __half g_xc  [M2*DIi];
__device__ float  g_proj[M2*64];          // [xd(32) | B(16) | C(16)] fp32
__device__ __half g_projh[M2*64];         // half mirror for gemm_dt A-path
__device__ float  g_projp[KS*M2*64];      // split-K partials (fp32)
__device__ __half g_delta[M2*DIi];
__device__ __half g_yg  [M2*DIi];
__device__ float  g_P   [NSEQ*NCH*DIi*NN];
__device__ float  g_Q   [NSEQ*NCH*DIi*NN];
__device__ float  g_Hin [NSEQ*NCH*DIi*NN];

__device__ __forceinline__ float siluf(float x){ return x / (1.f + __expf(-x)); }
__device__ __forceinline__ float spf(float a){ return (a > 20.f) ? a : log1pf(__expf(a)); }

__device__ __forceinline__ unsigned h2pack(float a, float b){
  __half2 h = __floats2half2_rn(a, b);
  return *reinterpret_cast<unsigned*>(&h);
}
__device__ __forceinline__ float4 h4load(const __half* p){
  uint2 u = *(const uint2*)p;
  float2 fa = __half22float2(*(__half2*)&u.x);
  float2 fb = __half22float2(*(__half2*)&u.y);
  return make_float4(fa.x, fa.y, fb.x, fb.y);
}
__device__ __forceinline__ void h4store(__half* p, float4 v){
  uint2 u; u.x = h2pack(v.x, v.y); u.y = h2pack(v.z, v.w);
  *(uint2*)p = u;
}

#define MMA16(c, a, b)                                                       \
  asm volatile("mma.sync.aligned.m16n8k16.row.col.f32.f16.f16.f32 "          \
               "{%0,%1,%2,%3},{%4,%5,%6,%7},{%8,%9},{%0,%1,%2,%3};"          \
               : "+f"(c[0]), "+f"(c[1]), "+f"(c[2]), "+f"(c[3])              \
               : "r"(a[0]), "r"(a[1]), "r"(a[2]), "r"(a[3]),                 \
                 "r"(b[0]), "r"(b[1]))

// ---------------- init: fwd + reversed copies ----------------
__global__ void k_init(const float* __restrict__ x){
  int idx = blockIdx.x*256 + threadIdx.x;       // M2*64 float4s
  int col = idx & 63;
  int m   = idx >> 6;                           // 0..8191
  int half = m >> 12;
  int b = (m >> 11) & 1, s = m & (Ss-1);
  int ms = b*Ss + (half ? (Ss-1-s) : s);
  reinterpret_cast<float4*>(g_res)[m*64+col] =
      reinterpret_cast<const float4*>(x)[ms*64+col];
}

// ======================================================================
// FP16 tensor-core GEMM core, double-buffered, mma.m16n8k16.
// Block tile 64(M) x 64(N), 256 threads = 8 warps (4 M x 2 N),
// warp tile 16 x 32 (4 mma per chunk). K-chunk = 16.
// Fragments stored per-lane contiguous -> LDS.128/LDS.64 conflict-free.
// A staging: thread t covers (row = t>>2, k-quad = t&3) -> 2 STS.32.
// ======================================================================
#define TC_DECL()                                                     \
  __shared__ __align__(16) unsigned Af[2][512];                       \
  __shared__ __align__(16) unsigned Bf[2][512];                       \
  const int t = threadIdx.x;                                          \
  const int lane = t & 31, wid = t >> 5;                              \
  const int wm = wid >> 1, wn = wid & 1;                              \
  const int s_r = t >> 2;           /* A staging row 0..63   */       \
  const int s_q = t & 3;            /* A staging k-quad 0..3 */       \
  const int s_bq = t >> 6;          /* B staging k-quad 0..3 */       \
  const int s_bn = t & 63;          /* B staging n 0..63     */       \
  const int aoff = (((s_r>>4)*32 + ((s_r&7)*4) + ((2*s_q)&3))*4)      \
                   + ((s_r>>3)&1) + 2*(s_q>>1);                       \
  float acc[4][4] = {};                                               \
  float4 raA; uint2 raH;                                              \
  float rb0, rb1, rb2, rb3;                                           \
  (void)raA; (void)raH;

#define TC_STAGE_B(buf) {                                             \
  int ln0 = (s_bn & 7)*4 + ((2*s_bq) & 3);                            \
  int rgB = s_bq >> 1;                                                \
  unsigned* bb = &Bf[buf][((s_bn >> 3)*32 + ln0)*2 + rgB];            \
  bb[0] = h2pack(rb0, rb1);                                           \
  bb[2] = h2pack(rb2, rb3); }

#define TC_STAGE_F(buf) {                                             \
  Af[buf][aoff]   = h2pack(raA.x, raA.y);                             \
  Af[buf][aoff+4] = h2pack(raA.z, raA.w);                             \
  TC_STAGE_B(buf) }

#define TC_STAGE_H(buf) {                                             \
  Af[buf][aoff]   = raH.x;                                            \
  Af[buf][aoff+4] = raH.y;                                            \
  TC_STAGE_B(buf) }

#define TC_COMP(buf) {                                                \
  unsigned a_[4]; unsigned b_[4][2];                                  \
  *(uint4*)a_ = *(const uint4*)&Af[buf][(wm*32 + lane)*4];            \
  _Pragma("unroll") for (int nt=0;nt<4;nt++)                          \
    *(uint2*)b_[nt] = *(const uint2*)&Bf[buf][((wn*4+nt)*32 + lane)*2]; \
  _Pragma("unroll") for (int nt=0;nt<4;nt++)                          \
    MMA16(acc[nt], a_, b_[nt]); }

#define TC_BODY_GEN(KT, STG)                                          \
  LOADA(0); LOADB(0);                                                 \
  STG(0);                                                             \
  if (16 < (KT)) { LOADA(16); LOADB(16); }                            \
  __syncthreads();                                                    \
  { int cur = 0;                                                      \
    _Pragma("unroll 1")                                               \
    for (int k0=0; k0<(KT); k0+=16){                                  \
      if (k0+16 < (KT)) STG(cur^1);                                   \
      if (k0+32 < (KT)) { LOADA(k0+32); LOADB(k0+32); }               \
      TC_COMP(cur);                                                   \
      __syncthreads();                                                \
      cur ^= 1;                                                       \
    } }

#define TC_BODY(KT)   TC_BODY_GEN(KT, TC_STAGE_F)
#define TC_BODY_H(KT) TC_BODY_GEN(KT, TC_STAGE_H)

// generic epilogue coordinates
#define TC_R(nt)  (row0 + wm*16 + (lane>>2))
#define TC_C(nt)  (col0 + wn*32 + (nt)*8 + (lane&3)*2)

// in_proj with fused LayerNorm:
//   LN(g_res)[8192,256] @ in_w[256,1024] -> xs | z (half)   per-half weights
__global__ void k_gemm_in(const float* __restrict__ W0, const float* __restrict__ W1,
                          const float* __restrict__ g0, const float* __restrict__ bt0,
                          const float* __restrict__ g1, const float* __restrict__ bt1){
  int col0 = blockIdx.x*64, row0 = blockIdx.y*64;
  int half = row0 >> 12;
  const float* W  = half ? W1  : W0;
  const float* gm = half ? g1  : g0;
  const float* bb = half ? bt1 : bt0;
  __shared__ float sG[DMm], sBt[DMm];
  TC_DECL();
  sG[t] = gm[t]; sBt[t] = bb[t];
  const float* rowp = g_res + (size_t)(row0 + s_r)*DMm;
  // per-row LN stats: 4 threads (k-quads) per row, reduce over quad
  float sum = 0.f, sq = 0.f;
  #pragma unroll
  for (int j=0;j<16;j++){
    float4 v = *(const float4*)&rowp[j*16 + s_q*4];
    sum += v.x+v.y+v.z+v.w;
    sq  += v.x*v.x+v.y*v.y+v.z*v.z+v.w*v.w;
  }
  sum += __shfl_xor_sync(~0u, sum, 1);  sq += __shfl_xor_sync(~0u, sq, 1);
  sum += __shfl_xor_sync(~0u, sum, 2);  sq += __shfl_xor_sync(~0u, sq, 2);
  float mean = sum*(1.f/DMm);
  float rstd = rsqrtf(sq*(1.f/DMm) - mean*mean + 1e-5f);
  __syncthreads();   // sG/sBt visible
#define LOADA(k0_) { int kk_=(k0_)+s_q*4;                                          \
    raA = *(const float4*)&rowp[kk_];                                              \
    raA.x=(raA.x-mean)*rstd*sG[kk_+0]+sBt[kk_+0];                                  \
    raA.y=(raA.y-mean)*rstd*sG[kk_+1]+sBt[kk_+1];                                  \
    raA.z=(raA.z-mean)*rstd*sG[kk_+2]+sBt[kk_+2];                                  \
    raA.w=(raA.w-mean)*rstd*sG[kk_+3]+sBt[kk_+3]; }
#define LOADB(k0_) { int kb_ = (k0_) + s_bq*4;                                     \
                     rb0 = W[(size_t)(kb_+0)*(2*DIi) + col0 + s_bn];               \
                     rb1 = W[(size_t)(kb_+1)*(2*DIi) + col0 + s_bn];               \
                     rb2 = W[(size_t)(kb_+2)*(2*DIi) + col0 + s_bn];               \
                     rb3 = W[(size_t)(kb_+3)*(2*DIi) + col0 + s_bn]; }
  TC_BODY(DMm);
#undef LOADA
#undef LOADB
  __half* dst = (col0 < DIi) ? g_xs : g_z;
  int cb = (col0 < DIi) ? col0 : col0 - DIi;
  #pragma unroll
  for (int nt=0;nt<4;nt++){
    int r = row0 + wm*16 + (lane>>2);
    int c = cb + wn*32 + nt*8 + (lane&3)*2;
    *(unsigned*)&dst[(size_t)r*DIi + c]     = h2pack(acc[nt][0], acc[nt][1]);
    *(unsigned*)&dst[(size_t)(r+8)*DIi + c] = h2pack(acc[nt][2], acc[nt][3]);
  }
}

// x-proj split-K: xc[8192,512](half) @ [xd(32)|xB(16)|xC(16)] -> projp[kz] (fp32)
__global__ void k_gemm_x(const float* __restrict__ xdw0, const float* __restrict__ xbw0,
                         const float* __restrict__ xcw0,
                         const float* __restrict__ xdw1, const float* __restrict__ xbw1,
                         const float* __restrict__ xcw1){
  int kz = blockIdx.x, row0 = blockIdx.y*64;
  int half = row0 >> 12;
  int kbase = kz*(DIi/KS);
  int col0 = 0;
  TC_DECL();
  (void)col0;
  const float* bsrc; int ldb, boff;
  if      (s_bn < 32){ bsrc = half?xdw1:xdw0; ldb = 32; boff = s_bn;      }
  else if (s_bn < 48){ bsrc = half?xbw1:xbw0; ldb = 16; boff = s_bn - 32; }
  else               { bsrc = half?xcw1:xcw0; ldb = 16; boff = s_bn - 48; }
#define LOADA(k0_) { raH = *(const uint2*)&g_xc[(size_t)(row0+s_r)*DIi + kbase+(k0_)+s_q*4]; }
#define LOADB(k0_) { int kb_ = kbase + (k0_) + s_bq*4;                                   \
                     rb0 = bsrc[(kb_+0)*ldb + boff];                                     \
                     rb1 = bsrc[(kb_+1)*ldb + boff];                                     \
                     rb2 = bsrc[(kb_+2)*ldb + boff];                                     \
                     rb3 = bsrc[(kb_+3)*ldb + boff]; }
  TC_BODY_H(DIi/KS);
#undef LOADA
#undef LOADB
  float* dst = g_projp + (size_t)kz*M2*64;
  #pragma unroll
  for (int nt=0;nt<4;nt++){
    int r = row0 + wm*16 + (lane>>2);
    int c = wn*32 + nt*8 + (lane&3)*2;
    *(float2*)&dst[(size_t)r*64 + c]     = make_float2(acc[nt][0], acc[nt][1]);
    *(float2*)&dst[(size_t)(r+8)*64 + c] = make_float2(acc[nt][2], acc[nt][3]);
  }
}

__global__ void k_xred(){
  int i = blockIdx.x*256 + threadIdx.x;   // M2*16 float4s
  float4 a = reinterpret_cast<const float4*>(g_projp)[i];
  float4 b = reinterpret_cast<const float4*>(g_projp + (size_t)M2*64)[i];
  float4 c = reinterpret_cast<const float4*>(g_projp + (size_t)2*M2*64)[i];
  float4 d = reinterpret_cast<const float4*>(g_projp + (size_t)3*M2*64)[i];
  float4 s = make_float4(a.x+b.x+c.x+d.x, a.y+b.y+c.y+d.y,
                         a.z+b.z+c.z+d.z, a.w+b.w+c.w+d.w);
  reinterpret_cast<float4*>(g_proj)[i] = s;
  h4store(&g_projh[i*4], s);
}

// delta: softplus(projh[:, :32] @ dtp_w[32,512] + dtp_b) -> g_delta (half)
__global__ void k_gemm_dt(const float* __restrict__ Wd0, const float* __restrict__ bd0,
                          const float* __restrict__ Wd1, const float* __restrict__ bd1){
  int col0 = blockIdx.x*64, row0 = blockIdx.y*64;
  int half = row0 >> 12;
  const float* Wd = half ? Wd1 : Wd0;
  const float* bd = half ? bd1 : bd0;
  TC_DECL();
#define LOADA(k0_) { raH = *(const uint2*)&g_projh[(size_t)(row0+s_r)*64 + (k0_)+s_q*4]; }
#define LOADB(k0_) { int kb_ = (k0_) + s_bq*4;                                      \
                     rb0 = Wd[(kb_+0)*DIi + col0 + s_bn];                           \
                     rb1 = Wd[(kb_+1)*DIi + col0 + s_bn];                           \
                     rb2 = Wd[(kb_+2)*DIi + col0 + s_bn];                           \
                     rb3 = Wd[(kb_+3)*DIi + col0 + s_bn]; }
  TC_BODY_H(RR);
#undef LOADA
#undef LOADB
  #pragma unroll
  for (int nt=0;nt<4;nt++){
    int r = row0 + wm*16 + (lane>>2);
    int c = col0 + wn*32 + nt*8 + (lane&3)*2;
    float b0 = bd[c], b1 = bd[c+1];
    *(unsigned*)&g_delta[(size_t)r*DIi + c] =
        h2pack(spf(acc[nt][0]+b0), spf(acc[nt][1]+b1));
    *(unsigned*)&g_delta[(size_t)(r+8)*DIi + c] =
        h2pack(spf(acc[nt][2]+b0), spf(acc[nt][3]+b1));
  }
}

// out_proj: yg[8192,512](half) @ out_w[512,256] + residual (in place on g_res)
__global__ void k_gemm_out(const float* __restrict__ W0, const float* __restrict__ W1){
  int col0 = blockIdx.x*64, row0 = blockIdx.y*64;
  int half = row0 >> 12;
  const float* W = half ? W1 : W0;
  TC_DECL();
#define LOADA(k0_) { raH = *(const uint2*)&g_yg[(size_t)(row0+s_r)*DIi + (k0_)+s_q*4]; }
#define LOADB(k0_) { int kb_ = (k0_) + s_bq*4;                                     \
                     rb0 = W[(kb_+0)*DMm + col0 + s_bn];                           \
                     rb1 = W[(kb_+1)*DMm + col0 + s_bn];                           \
                     rb2 = W[(kb_+2)*DMm + col0 + s_bn];                           \
                     rb3 = W[(kb_+3)*DMm + col0 + s_bn]; }
  TC_BODY_H(DIi);
#undef LOADA
#undef LOADB
  #pragma unroll
  for (int nt=0;nt<4;nt++){
    int r = row0 + wm*16 + (lane>>2);
    int c = col0 + wn*32 + nt*8 + (lane&3)*2;
    float2 o0 = *(const float2*)&g_res[(size_t)r*DMm + c];
    float2 o1 = *(const float2*)&g_res[(size_t)(r+8)*DMm + c];
    *(float2*)&g_res[(size_t)r*DMm + c] =
        make_float2(acc[nt][0]+o0.x, acc[nt][1]+o0.y);
    *(float2*)&g_res[(size_t)(r+8)*DMm + c] =
        make_float2(acc[nt][2]+o1.x, acc[nt][3]+o1.y);
  }
}

// merge: concat(res_half0, res_half1_reversed)[4096,512] @ merge_w[512,256] -> out
__global__ void k_merge(const float* __restrict__ W, float* __restrict__ out){
  int col0 = blockIdx.x*64, row0 = blockIdx.y*64;
  TC_DECL();
  int r_ = row0 + s_r;                 // 0..4095
  int b_ = r_ >> 11, s_ = r_ & (Ss-1);
  int rrev = MM + b_*Ss + (Ss-1-s_);   // reversed row in half 1
#define LOADA(k0_) { int kk_ = (k0_)+s_q*4;                                        \
    raA = *(const float4*)((kk_ < DMm) ? (g_res + (size_t)r_*DMm + kk_)            \
                                       : (g_res + (size_t)rrev*DMm + kk_-DMm)); }
#define LOADB(k0_) { int kb_ = (k0_) + s_bq*4;                                     \
                     rb0 = W[(kb_+0)*DMm + col0 + s_bn];                           \
                     rb1 = W[(kb_+1)*DMm + col0 + s_bn];                           \
                     rb2 = W[(kb_+2)*DMm + col0 + s_bn];                           \
                     rb3 = W[(kb_+3)*DMm + col0 + s_bn]; }
  TC_BODY(2*DMm);
#undef LOADA
#undef LOADB
  #pragma unroll
  for (int nt=0;nt<4;nt++){
    int r = row0 + wm*16 + (lane>>2);
    int c = col0 + wn*32 + nt*8 + (lane&3)*2;
    *(float2*)&out[(size_t)r*DMm + c]     = make_float2(acc[nt][0], acc[nt][1]);
    *(float2*)&out[(size_t)(r+8)*DMm + c] = make_float2(acc[nt][2], acc[nt][3]);
  }
}

// ---------------- causal depthwise conv (K=4) + silu, half I/O ----------------
__global__ void k_conv(const float* __restrict__ cw0, const float* __restrict__ cb0,
                       const float* __restrict__ cw1, const float* __restrict__ cb1){
  int idx = blockIdx.x*256 + threadIdx.x;   // (M2/4)*128
  int d4 = idx & 127, g = idx >> 7;         // g in [0, M2/4)
  int b2 = g >> 9, sg = g & 511;            // seq 0..3, group within seq
  int half = b2 >> 1;
  const float* cw = half ? cw1 : cw0;
  const float* cb = half ? cb1 : cb0;
  int m0 = b2*Ss + sg*4;
  int d = d4*4;
  float4 w0 = *(const float4*)(cw + (d+0)*4);
  float4 w1 = *(const float4*)(cw + (d+1)*4);
  float4 w2 = *(const float4*)(cw + (d+2)*4);
  float4 w3 = *(const float4*)(cw + (d+3)*4);
  float4 bv = *(const float4*)(cb + d);
  float4 x0, x1, x2;
  if (sg > 0){
    x0 = h4load(&g_xs[(size_t)(m0-3)*DIi + d]);
    x1 = h4load(&g_xs[(size_t)(m0-2)*DIi + d]);
    x2 = h4load(&g_xs[(size_t)(m0-1)*DIi + d]);
  } else {
    x0 = x1 = x2 = make_float4(0.f,0.f,0.f,0.f);
  }
  #pragma unroll
  for (int s=0;s<4;s++){
    float4 x3 = h4load(&g_xs[(size_t)(m0+s)*DIi + d]);
    float4 a;
    a.x = bv.x + w0.x*x0.x + w0.y*x1.x + w0.z*x2.x + w0.w*x3.x;
    a.y = bv.y + w1.x*x0.y + w1.y*x1.y + w1.z*x2.y + w1.w*x3.y;
    a.z = bv.z + w2.x*x0.z + w2.y*x1.z + w2.z*x2.z + w2.w*x3.z;
    a.w = bv.w + w3.x*x0.w + w3.y*x1.w + w3.z*x2.w + w3.w*x3.w;
    a.x = siluf(a.x); a.y = siluf(a.y); a.z = siluf(a.z); a.w = siluf(a.w);
    h4store(&g_xc[(size_t)(m0+s)*DIi + d], a);
    x0 = x1; x1 = x2; x2 = x3;
  }
}

// dA helper: if A[n] == -(n+1) (the actual dataset), dA_n = r^(n+1) with
// r = exp(-delta): 1 MUFU + 15 FMUL instead of 16 MUFU.
__device__ __forceinline__ void dA_compute(float* dAv, const float* A,
                                           float dlt, bool fast){
  if (fast){
    float r = __expf(-dlt);
    dAv[0] = r; dAv[1] = r*r;
    #pragma unroll
    for (int n=2;n<NN;n++) dAv[n] = dAv[n>>1]*dAv[(n-1)>>1];
  } else {
    #pragma unroll
    for (int n=0;n<NN;n++) dAv[n] = __expf(dlt*A[n]);
  }
}

__device__ __forceinline__ bool a_fast(const float* A){
  bool f = true;
  #pragma unroll
  for (int n=0;n<NN;n++) f = f && (fabsf(A[n] + (float)(n+1)) < 1e-5f*(n+1));
  return f;
}

// ---------------- chunked scan phase 1 ----------------
__global__ void k_scan1(const float* __restrict__ Alog0, const float* __restrict__ Alog1){
  __shared__ float sB[CHUNK][NN];
  int blk = blockIdx.x;               // 2 * NSEQ*NCH = 512
  int bc_ = blk >> 1;                 // 0..255
  int seq = bc_ >> 6, c = bc_ & 63;
  int half = seq >> 1;
  const float* Alog = half ? Alog1 : Alog0;
  int d = (blk & 1)*256 + threadIdx.x;
  int m0 = seq*Ss + c*CHUNK;
  { int i0 = threadIdx.x, i1 = threadIdx.x + 256;
    sB[i0>>4][i0&15] = g_proj[(size_t)(m0+(i0>>4))*64 + 32 + (i0&15)];
    sB[i1>>4][i1&15] = g_proj[(size_t)(m0+(i1>>4))*64 + 32 + (i1&15)]; }
  float A[NN];
  #pragma unroll
  for (int n=0;n<NN;n++) A[n] = -__expf(Alog[d*NN + n]);
  bool fast = a_fast(A);
  __syncthreads();
  float h[NN];
  #pragma unroll
  for (int n=0;n<NN;n++) h[n] = 0.f;
  float sd = 0.f;
  #pragma unroll 1
  for (int s=0;s<CHUNK;s++){
    size_t m = m0 + s;
    float dlt = __half2float(g_delta[m*DIi + d]);
    float dx  = dlt * __half2float(g_xc[m*DIi + d]);
    sd += dlt;
    float dAv[NN];
    dA_compute(dAv, A, dlt, fast);
    #pragma unroll
    for (int n=0;n<NN;n++) h[n] = dAv[n]*h[n] + dx*sB[s][n];
  }
  size_t base = ((size_t)bc_*DIi + d)*NN;
  float Pv[NN];
  dA_compute(Pv, A, sd, fast);
  #pragma unroll
  for (int n=0;n<NN;n++){ g_Q[base+n]=h[n]; g_P[base+n]=Pv[n]; }
}

// ---------------- phase 2: combine across chunks ----------------
__global__ void k_comb(){
  int i = blockIdx.x*128 + threadIdx.x;     // NSEQ*DIi*NN = 32768
  int n = i & 15, d = (i >> 4) & (DIi-1), seq = i >> 13;
  float H = 0.f;
  for (int c=0;c<NCH;c++){
    size_t idx = (((size_t)(seq*NCH+c))*DIi + d)*NN + n;
    g_Hin[idx] = H;
    H = g_P[idx]*H + g_Q[idx];
  }
}

// ---------------- phase 3: replay + gated output ----------------
__global__ void k_scan2(const float* __restrict__ Alog0, const float* __restrict__ Alog1,
                        const float* __restrict__ Dp0, const float* __restrict__ Dp1){
  __shared__ float sB[CHUNK][NN];
  __shared__ float sC[CHUNK][NN];
  int blk = blockIdx.x;
  int bc_ = blk >> 1;
  int seq = bc_ >> 6, c = bc_ & 63;
  int half = seq >> 1;
  const float* Alog = half ? Alog1 : Alog0;
  const float* Dp   = half ? Dp1   : Dp0;
  int d = (blk & 1)*256 + threadIdx.x;
  int m0 = seq*Ss + c*CHUNK;
  { int i0 = threadIdx.x, i1 = threadIdx.x + 256;
    sB[i0>>4][i0&15] = g_proj[(size_t)(m0+(i0>>4))*64 + 32 + (i0&15)];
    sB[i1>>4][i1&15] = g_proj[(size_t)(m0+(i1>>4))*64 + 32 + (i1&15)];
    sC[i0>>4][i0&15] = g_proj[(size_t)(m0+(i0>>4))*64 + 48 + (i0&15)];
    sC[i1>>4][i1&15] = g_proj[(size_t)(m0+(i1>>4))*64 + 48 + (i1&15)]; }
  float A[NN];
  #pragma unroll
  for (int n=0;n<NN;n++) A[n] = -__expf(Alog[d*NN + n]);
  bool fast = a_fast(A);
  float h[NN];
  size_t base = ((size_t)bc_*DIi + d)*NN;
  #pragma unroll
  for (int n=0;n<NN;n++) h[n] = g_Hin[base+n];
  float Dv = Dp[d];
  __syncthreads();
  #pragma unroll 1
  for (int s=0;s<CHUNK;s++){
    size_t m = m0 + s;
    float dlt = __half2float(g_delta[m*DIi + d]);
    float x   = __half2float(g_xc[m*DIi + d]);
    float dx  = dlt * x;
    float dAv[NN];
    dA_compute(dAv, A, dlt, fast);
    float y = 0.f;
    #pragma unroll
    for (int n=0;n<NN;n++){
      h[n] = dAv[n]*h[n] + dx*sB[s][n];
      y += h[n]*sC[s][n];
    }
    y += Dv*x;
    float zv = __half2float(g_z[m*DIi + d]);
    g_yg[m*DIi + d] = __float2half(y * siluf(zv));
  }
}

// ---------------- driver ----------------
extern "C" void kernel_launch(void* const* d_in, const int* in_sizes, int n_in,
                              void* d_out, int out_size){
  const float* x      = (const float*)d_in[0];
  const float* in_w   = (const float*)d_in[1];
  const float* conv_w = (const float*)d_in[2];
  const float* conv_b = (const float*)d_in[3];
  const float* A_log  = (const float*)d_in[4];
  const float* xd_w   = (const float*)d_in[5];
  const float* xB_w   = (const float*)d_in[6];
  const float* xC_w   = (const float*)d_in[7];
  const float* dtp_w  = (const float*)d_in[8];
  const float* dtp_b  = (const float*)d_in[9];
  const float* Dp     = (const float*)d_in[10];
  const float* out_w  = (const float*)d_in[11];
  const float* ln_g   = (const float*)d_in[12];
  const float* ln_b   = (const float*)d_in[13];
  const float* merge_w= (const float*)d_in[14];
  float* out = (float*)d_out;

  k_init<<<M2*64/256, 256>>>(x);
  for (int bi=0; bi<2; bi++){
    int b0 = bi, b1 = 2 + bi;
    k_gemm_in <<<dim3(16,128), 256>>>(in_w + (size_t)b0*DMm*2*DIi,
                                      in_w + (size_t)b1*DMm*2*DIi,
                                      ln_g + b0*DMm, ln_b + b0*DMm,
                                      ln_g + b1*DMm, ln_b + b1*DMm);
    k_conv    <<<(M2/4)*128/256, 256>>>(conv_w + b0*DIi*4, conv_b + b0*DIi,
                                        conv_w + b1*DIi*4, conv_b + b1*DIi);
    k_gemm_x  <<<dim3(KS,128), 256>>>(xd_w + b0*DIi*RR, xB_w + b0*DIi*NN, xC_w + b0*DIi*NN,
                                      xd_w + b1*DIi*RR, xB_w + b1*DIi*NN, xC_w + b1*DIi*NN);
    k_xred    <<<M2*16/256, 256>>>();
    k_gemm_dt <<<dim3(8,128), 256>>>(dtp_w + b0*RR*DIi, dtp_b + b0*DIi,
                                     dtp_w + b1*RR*DIi, dtp_b + b1*DIi);
    k_scan1   <<<2*NSEQ*NCH, 256>>>(A_log + b0*DIi*NN, A_log + b1*DIi*NN);
    k_comb    <<<256, 128>>>();
    k_scan2   <<<2*NSEQ*NCH, 256>>>(A_log + b0*DIi*NN, A_log + b1*DIi*NN,
                                    Dp + b0*DIi, Dp + b1*DIi);
    k_gemm_out<<<dim3(4,128), 256>>>(out_w + (size_t)b0*DIi*DMm,
                                     out_w + (size_t)b1*DIi*DMm);
  }
  k_merge<<<dim3(4,64), 256>>>(merge_w, out);
}